// round 1
// baseline (speedup 1.0000x reference)
#include <cuda_runtime.h>

#define NB 8
#define LQ 256
#define LK 256
#define HH 256
#define DV 256
#define MASK_VALUE -1000000.0f

// Scratch (allocation-free rule: device globals)
__device__ float g_Qp[NB * LQ * HH];
__device__ float g_Kp[NB * LK * HH];
__device__ float g_S[NB * LQ * LK];

__device__ __forceinline__ float tanh_fast(float x) {
    float y;
    asm("tanh.approx.f32 %0, %1;" : "=f"(y) : "f"(x));
    return y;
}

// ---------------------------------------------------------------------------
// Projection: C[m][n] = sum_k X[m][k] * W[n][k]   (NT GEMM, M=2048,N=256,K=256)
// blockIdx.z == 0 -> queries @ W_q^T -> g_Qp ; z == 1 -> keyes @ W_k^T -> g_Kp
// ---------------------------------------------------------------------------
__global__ void proj_kernel(const float* __restrict__ Xq, const float* __restrict__ Wq,
                            const float* __restrict__ Xk, const float* __restrict__ Wk) {
    const float* X;
    const float* W;
    float* C;
    if (blockIdx.z == 0) { X = Xq; W = Wq; C = g_Qp; }
    else                 { X = Xk; W = Wk; C = g_Kp; }

    __shared__ float As[32][68];
    __shared__ float Bs[32][68];

    const int tid = threadIdx.x;
    const int tx = tid & 15;
    const int ty = tid >> 4;
    const int m0 = blockIdx.y * 64;
    const int n0 = blockIdx.x * 64;

    float acc[4][4] = {};

    for (int k0 = 0; k0 < 256; k0 += 32) {
        #pragma unroll
        for (int idx = tid; idx < 64 * 32; idx += 256) {
            int r = idx >> 5;
            int k = idx & 31;
            As[k][r] = X[(m0 + r) * 256 + k0 + k];
            Bs[k][r] = W[(n0 + r) * 256 + k0 + k];
        }
        __syncthreads();
        #pragma unroll
        for (int kk = 0; kk < 32; kk++) {
            float4 a = *(const float4*)&As[kk][ty * 4];
            float4 b = *(const float4*)&Bs[kk][tx * 4];
            acc[0][0] += a.x * b.x; acc[0][1] += a.x * b.y; acc[0][2] += a.x * b.z; acc[0][3] += a.x * b.w;
            acc[1][0] += a.y * b.x; acc[1][1] += a.y * b.y; acc[1][2] += a.y * b.z; acc[1][3] += a.y * b.w;
            acc[2][0] += a.z * b.x; acc[2][1] += a.z * b.y; acc[2][2] += a.z * b.z; acc[2][3] += a.z * b.w;
            acc[3][0] += a.w * b.x; acc[3][1] += a.w * b.y; acc[3][2] += a.w * b.z; acc[3][3] += a.w * b.w;
        }
        __syncthreads();
    }

    #pragma unroll
    for (int i = 0; i < 4; i++) {
        float4 v = make_float4(acc[i][0], acc[i][1], acc[i][2], acc[i][3]);
        *(float4*)&C[(m0 + ty * 4 + i) * 256 + n0 + tx * 4] = v;
    }
}

// ---------------------------------------------------------------------------
// Scores: S[b][q][k] = sum_h Wv[h] * tanh(Qp[b][q][h] + Kp[b][k][h]),
// masked to MASK_VALUE where k >= valid_len[b]. Fully-masked 32x32 tiles skip
// all compute.
// ---------------------------------------------------------------------------
__global__ void scores_kernel(const float* __restrict__ Wv,
                              const int* __restrict__ vlens) {
    const int b = blockIdx.z;
    const int q0 = blockIdx.y * 32;
    const int k0 = blockIdx.x * 32;
    const int tid = threadIdx.x;
    const int tx = tid & 15;
    const int ty = tid >> 4;
    const int vl = vlens[b];
    float* S = g_S + b * LQ * LK;

    if (k0 >= vl) {
        // entire tile masked: write constant, skip all tanh work
        const float2 mv = make_float2(MASK_VALUE, MASK_VALUE);
        #pragma unroll
        for (int i = 0; i < 2; i++)
            *(float2*)&S[(q0 + ty * 2 + i) * LK + k0 + tx * 2] = mv;
        return;
    }

    __shared__ float Qs[64][34];
    __shared__ float Ks[64][34];
    __shared__ float sWv[256];

    sWv[tid] = Wv[tid];

    const float* Qb = g_Qp + (b * LQ + q0) * HH;
    const float* Kb = g_Kp + (b * LK + k0) * HH;

    float a00 = 0.f, a01 = 0.f, a10 = 0.f, a11 = 0.f;

    for (int h0 = 0; h0 < HH; h0 += 64) {
        #pragma unroll
        for (int idx = tid; idx < 32 * 64; idx += 256) {
            int r = idx >> 6;
            int h = idx & 63;
            Qs[h][r] = Qb[r * HH + h0 + h];
            Ks[h][r] = Kb[r * HH + h0 + h];
        }
        __syncthreads();
        #pragma unroll 8
        for (int h = 0; h < 64; h++) {
            float2 qv = *(const float2*)&Qs[h][ty * 2];
            float2 kv = *(const float2*)&Ks[h][tx * 2];
            float wv = sWv[h0 + h];
            a00 += wv * tanh_fast(qv.x + kv.x);
            a01 += wv * tanh_fast(qv.x + kv.y);
            a10 += wv * tanh_fast(qv.y + kv.x);
            a11 += wv * tanh_fast(qv.y + kv.y);
        }
        __syncthreads();
    }

    const int kA = k0 + tx * 2;
    const int kB = kA + 1;
    const int qA = q0 + ty * 2;
    const int qB = qA + 1;
    S[qA * LK + kA] = (kA < vl) ? a00 : MASK_VALUE;
    S[qA * LK + kB] = (kB < vl) ? a01 : MASK_VALUE;
    S[qB * LK + kA] = (kA < vl) ? a10 : MASK_VALUE;
    S[qB * LK + kB] = (kB < vl) ? a11 : MASK_VALUE;
}

// ---------------------------------------------------------------------------
// Softmax over axis=1 (QUERY axis) per (b, k) column — reference quirk.
// Block: 32 k-columns x 8 q-parallel threads. In-place on g_S.
// ---------------------------------------------------------------------------
__global__ void softmax_kernel() {
    const int b = blockIdx.y;
    const int tx = threadIdx.x & 31;
    const int ty = threadIdx.x >> 5;  // 0..7
    const int k = blockIdx.x * 32 + tx;
    float* S = g_S + b * LQ * LK;

    float vals[32];
    float m = -3.4e38f;
    #pragma unroll
    for (int i = 0; i < 32; i++) {
        vals[i] = S[(i * 8 + ty) * LK + k];
        m = fmaxf(m, vals[i]);
    }

    __shared__ float red[8][33];
    red[ty][tx] = m;
    __syncthreads();
    float M = red[0][tx];
    #pragma unroll
    for (int t = 1; t < 8; t++) M = fmaxf(M, red[t][tx]);
    __syncthreads();

    float s = 0.f;
    #pragma unroll
    for (int i = 0; i < 32; i++) {
        vals[i] = __expf(vals[i] - M);
        s += vals[i];
    }
    red[ty][tx] = s;
    __syncthreads();
    float SUM = 0.f;
    #pragma unroll
    for (int t = 0; t < 8; t++) SUM += red[t][tx];

    const float inv = 1.0f / SUM;
    #pragma unroll
    for (int i = 0; i < 32; i++)
        S[(i * 8 + ty) * LK + k] = vals[i] * inv;
}

// ---------------------------------------------------------------------------
// Output GEMM: out[b][q][d] = sum_k Attn[b][q][k] * V[b][k][d]  (NN, per batch)
// ---------------------------------------------------------------------------
__global__ void out_kernel(const float* __restrict__ Vv, float* __restrict__ out) {
    const int b = blockIdx.z;
    const int q0 = blockIdx.y * 64;
    const int d0 = blockIdx.x * 64;
    const int tid = threadIdx.x;
    const int tx = tid & 15;
    const int ty = tid >> 4;

    const float* A = g_S + b * LQ * LK;
    const float* V = Vv + b * LK * DV;

    __shared__ float As[32][68];
    __shared__ float Vs[32][68];

    float acc[4][4] = {};

    for (int k0 = 0; k0 < LK; k0 += 32) {
        #pragma unroll
        for (int idx = tid; idx < 64 * 32; idx += 256) {
            int r = idx >> 5;   // q-row within tile
            int k = idx & 31;
            As[k][r] = A[(q0 + r) * LK + k0 + k];
        }
        #pragma unroll
        for (int idx = tid; idx < 32 * 64; idx += 256) {
            int kk = idx >> 6;  // k-row within tile
            int d = idx & 63;
            Vs[kk][d] = V[(k0 + kk) * DV + d0 + d];
        }
        __syncthreads();
        #pragma unroll
        for (int kk = 0; kk < 32; kk++) {
            float4 a = *(const float4*)&As[kk][ty * 4];
            float4 v = *(const float4*)&Vs[kk][tx * 4];
            acc[0][0] += a.x * v.x; acc[0][1] += a.x * v.y; acc[0][2] += a.x * v.z; acc[0][3] += a.x * v.w;
            acc[1][0] += a.y * v.x; acc[1][1] += a.y * v.y; acc[1][2] += a.y * v.z; acc[1][3] += a.y * v.w;
            acc[2][0] += a.z * v.x; acc[2][1] += a.z * v.y; acc[2][2] += a.z * v.z; acc[2][3] += a.z * v.w;
            acc[3][0] += a.w * v.x; acc[3][1] += a.w * v.y; acc[3][2] += a.w * v.z; acc[3][3] += a.w * v.w;
        }
        __syncthreads();
    }

    #pragma unroll
    for (int i = 0; i < 4; i++) {
        float4 v = make_float4(acc[i][0], acc[i][1], acc[i][2], acc[i][3]);
        *(float4*)&out[b * LQ * DV + (q0 + ty * 4 + i) * DV + d0 + tx * 4] = v;
    }
}

extern "C" void kernel_launch(void* const* d_in, const int* in_sizes, int n_in,
                              void* d_out, int out_size) {
    const float* queries    = (const float*)d_in[0];
    const float* keyes      = (const float*)d_in[1];
    const float* values     = (const float*)d_in[2];
    const int*   valid_lens = (const int*)d_in[3];
    const float* W_q        = (const float*)d_in[4];
    const float* W_k        = (const float*)d_in[5];
    const float* W_v        = (const float*)d_in[6];
    float* out = (float*)d_out;

    proj_kernel<<<dim3(4, 32, 2), 256>>>(queries, W_q, keyes, W_k);
    scores_kernel<<<dim3(8, 8, 8), 256>>>(W_v, valid_lens);
    softmax_kernel<<<dim3(8, 8), 256>>>();
    out_kernel<<<dim3(4, 4, 8), 256>>>(values, out);
}